// round 1
// baseline (speedup 1.0000x reference)
#include <cuda_runtime.h>
#include <math.h>

#define Bsz 16384
#define Hd  1024
#define Cc  2
#define PPCc 24
#define Pp  48
#define EPSf 1e-4f

// Output layout (concatenated reference tuple, all fp32):
//   pos      [B,1]   at 0
//   shared   [B,H]   at B
//   logits   [B,C]   at B + B*H
//   distance [B,P]   at B + B*H + B*C
#define POS_OFF    ((size_t)0)
#define SHARED_OFF ((size_t)Bsz)
#define LOGITS_OFF (SHARED_OFF + (size_t)Bsz * Hd)
#define DIST_OFF   (LOGITS_OFF + (size_t)Bsz * Cc)

// Scratch (no device allocs allowed)
__device__ float g_p2[Pp];
__device__ float g_simSum[Pp];
__device__ int   g_jstar;
__device__ float g_u[Hd];

// ---------------------------------------------------------------------------
// Kernel 1: block 0 zeroes accumulators; blocks 1..48 compute ||proto_p||^2
// ---------------------------------------------------------------------------
__global__ void k_init(const float* __restrict__ protos) {
    const int b   = blockIdx.x;
    const int tid = threadIdx.x;
    if (b == 0) {
        if (tid < Pp) g_simSum[tid] = 0.f;
        for (int i = tid; i < Hd; i += blockDim.x) g_u[i] = 0.f;
        return;
    }
    const int p = b - 1;
    const float* pr = protos + (size_t)p * Hd;
    float s = 0.f;
    for (int t = tid; t < Hd; t += 256) { float v = pr[t]; s = fmaf(v, v, s); }
    __shared__ float red[8];
    for (int o = 16; o; o >>= 1) s += __shfl_xor_sync(0xffffffffu, s, o);
    const int lane = tid & 31, w = tid >> 5;
    if (lane == 0) red[w] = s;
    __syncthreads();
    if (w == 0) {
        s = (lane < 8) ? red[lane] : 0.f;
        for (int o = 4; o; o >>= 1) s += __shfl_xor_sync(0xffffffffu, s, o);
        if (lane == 0) g_p2[p] = s;
    }
}

// ---------------------------------------------------------------------------
// Kernel 2: distance GEMM (64 rows x 48 protos per block), similarity,
// logits, distance write, per-proto similarity column sums.
// 256 threads = 16x16; thread tile 4 rows x 3 protos; K-tiles of 32.
// ---------------------------------------------------------------------------
__global__ __launch_bounds__(256) void k_dist(
    const float* __restrict__ x, const float* __restrict__ protos,
    const float* __restrict__ llw, float* __restrict__ out) {
    __shared__ float xs[64 * 32];
    __shared__ float ps[48 * 36];     // pad to 36 for conflict spread
    __shared__ float x2s[64];
    __shared__ float p2s[48];
    __shared__ float wks[96];
    __shared__ float dbuf[64 * 48];
    __shared__ float logit_s[128];
    __shared__ float simPart[48];

    const int tid  = threadIdx.x;
    const int tx   = tid & 15, ty = tid >> 4;
    const int row0 = blockIdx.x * 64;
    const int lane = tid & 31, warp = tid >> 5;

    if (tid < 48) { simPart[tid] = 0.f; p2s[tid] = g_p2[tid]; }
    if (tid < 128) logit_s[tid] = 0.f;
    if (tid < 96)  wks[tid] = llw[tid];

    // x2 prepass: warp handles 8 rows
#pragma unroll
    for (int i = 0; i < 8; i++) {
        const int r = warp * 8 + i;
        const float* xr = x + (size_t)(row0 + r) * Hd;
        float s = 0.f;
        for (int t = lane; t < Hd; t += 32) { float v = __ldg(xr + t); s = fmaf(v, v, s); }
        for (int o = 16; o; o >>= 1) s += __shfl_xor_sync(0xffffffffu, s, o);
        if (lane == 0) x2s[r] = s;
    }

    float acc[4][3];
#pragma unroll
    for (int i = 0; i < 4; i++)
#pragma unroll
        for (int j = 0; j < 3; j++) acc[i][j] = 0.f;

    for (int kt = 0; kt < Hd; kt += 32) {
        __syncthreads();
        // load x tile: 64x32 floats, 2 float4 per thread
#pragma unroll
        for (int s = 0; s < 2; s++) {
            const int i  = tid + s * 256;
            const int r  = i >> 3;
            const int k4 = (i & 7) << 2;
            *(float4*)&xs[r * 32 + k4] =
                *(const float4*)(x + (size_t)(row0 + r) * Hd + kt + k4);
        }
        // load proto tile: 48x32 floats, 6 per thread
#pragma unroll
        for (int s = 0; s < 6; s++) {
            const int i = tid + s * 256;
            const int p = i >> 5, k = i & 31;
            ps[p * 36 + k] = __ldg(protos + (size_t)p * Hd + kt + k);
        }
        __syncthreads();
#pragma unroll
        for (int kk = 0; kk < 32; kk += 4) {
            float xv[4][4], pv[3][4];
#pragma unroll
            for (int rr = 0; rr < 4; rr++)
                *(float4*)xv[rr] = *(const float4*)&xs[(ty * 4 + rr) * 32 + kk];
#pragma unroll
            for (int pp = 0; pp < 3; pp++)
                *(float4*)pv[pp] = *(const float4*)&ps[(tx * 3 + pp) * 36 + kk];
#pragma unroll
            for (int rr = 0; rr < 4; rr++)
#pragma unroll
                for (int pp = 0; pp < 3; pp++)
#pragma unroll
                    for (int q = 0; q < 4; q++)
                        acc[rr][pp] = fmaf(xv[rr][q], pv[pp][q], acc[rr][pp]);
        }
    }
    __syncthreads();

    // epilogue
    float simAcc[3] = {0.f, 0.f, 0.f};
    float lg[4][2];
#pragma unroll
    for (int rr = 0; rr < 4; rr++) { lg[rr][0] = 0.f; lg[rr][1] = 0.f; }
#pragma unroll
    for (int rr = 0; rr < 4; rr++) {
        const int r = ty * 4 + rr;
#pragma unroll
        for (int pp = 0; pp < 3; pp++) {
            const int p = tx * 3 + pp;
            const float d = fmaf(-2.f, acc[rr][pp], x2s[r] + p2s[p]);
            dbuf[r * 48 + p] = d;
            const float sim = logf((d + 1.f) / (d + EPSf));
            lg[rr][0] = fmaf(sim, wks[p], lg[rr][0]);
            lg[rr][1] = fmaf(sim, wks[48 + p], lg[rr][1]);
            simAcc[pp] += sim;
        }
    }
#pragma unroll
    for (int rr = 0; rr < 4; rr++) {
        atomicAdd(&logit_s[(ty * 4 + rr) * 2 + 0], lg[rr][0]);
        atomicAdd(&logit_s[(ty * 4 + rr) * 2 + 1], lg[rr][1]);
    }
#pragma unroll
    for (int pp = 0; pp < 3; pp++)
        atomicAdd(&simPart[tx * 3 + pp], simAcc[pp]);
    __syncthreads();

    // distance: coalesced float4 store from smem staging
    float* dd = out + DIST_OFF + (size_t)row0 * 48;
#pragma unroll
    for (int s = 0; s < 3; s++) {
        const int i = tid + s * 256;
        *(float4*)(dd + (size_t)i * 4) = *(float4*)&dbuf[i * 4];
    }
    if (tid < 128) out[LOGITS_OFF + (size_t)row0 * 2 + tid] = logit_s[tid];
    if (tid < 48) atomicAdd(&g_simSum[tid], simPart[tid]);
}

// ---------------------------------------------------------------------------
// Kernel 3: argmax over the class's 24 prototype column sums (first-max ties)
// ---------------------------------------------------------------------------
__global__ void k_argmax(const int* __restrict__ flag) {
    const int idx  = (flag[0] != 0) ? 1 : 0;
    const int lane = threadIdx.x;
    float v = (lane < PPCc) ? g_simSum[idx * PPCc + lane] : -INFINITY;
    int bj = lane;
    for (int o = 16; o; o >>= 1) {
        const float ov = __shfl_xor_sync(0xffffffffu, v, o);
        const int   oj = __shfl_xor_sync(0xffffffffu, bj, o);
        if (ov > v || (ov == v && oj < bj)) { v = ov; bj = oj; }
    }
    if (lane == 0) g_jstar = idx * PPCc + bj;
}

// ---------------------------------------------------------------------------
// Kernel 4: u[j] = sum_i v_i * W[i][j], v = protos[g_jstar]
// 32 blocks each own 32 rows of W; float atomics into g_u
// ---------------------------------------------------------------------------
__global__ __launch_bounds__(256) void k_u(
    const float* __restrict__ protos, const float* __restrict__ W) {
    __shared__ float vsh[32];
    const int b = blockIdx.x, t = threadIdx.x;
    if (t < 32) vsh[t] = protos[(size_t)g_jstar * Hd + b * 32 + t];
    __syncthreads();
    float a0 = 0.f, a1 = 0.f, a2 = 0.f, a3 = 0.f;
    const float* Wp = W + (size_t)b * 32 * Hd + (size_t)t * 4;
#pragma unroll 8
    for (int i = 0; i < 32; i++) {
        const float4 w = *(const float4*)(Wp + (size_t)i * Hd);
        const float vi = vsh[i];
        a0 = fmaf(vi, w.x, a0);
        a1 = fmaf(vi, w.y, a1);
        a2 = fmaf(vi, w.z, a2);
        a3 = fmaf(vi, w.w, a3);
    }
    atomicAdd(&g_u[t * 4 + 0], a0);
    atomicAdd(&g_u[t * 4 + 1], a1);
    atomicAdd(&g_u[t * 4 + 2], a2);
    atomicAdd(&g_u[t * 4 + 3], a3);
}

// ---------------------------------------------------------------------------
// Kernel 5: fused shared_user copy-out + pos[b] = dot(u, shared[b]) + bias
// 1 warp per row, 8 rows per block
// ---------------------------------------------------------------------------
__global__ __launch_bounds__(256) void k_pos(
    const float* __restrict__ shr, const float* __restrict__ bb,
    float* __restrict__ out) {
    __shared__ float us[Hd];
    for (int i = threadIdx.x; i < Hd; i += 256) us[i] = g_u[i];
    __syncthreads();
    const int warp = threadIdx.x >> 5, lane = threadIdx.x & 31;
    const int r = blockIdx.x * 8 + warp;
    const float4* src = (const float4*)(shr + (size_t)r * Hd);
    float4*       dst = (float4*)(out + SHARED_OFF + (size_t)r * Hd);
    const float4* uf  = (const float4*)us;
    float acc = 0.f;
#pragma unroll
    for (int t = lane; t < Hd / 4; t += 32) {
        const float4 v  = src[t];
        dst[t] = v;
        const float4 u4 = uf[t];
        acc = fmaf(v.x, u4.x, acc);
        acc = fmaf(v.y, u4.y, acc);
        acc = fmaf(v.z, u4.z, acc);
        acc = fmaf(v.w, u4.w, acc);
    }
    for (int o = 16; o; o >>= 1) acc += __shfl_xor_sync(0xffffffffu, acc, o);
    if (lane == 0) out[POS_OFF + r] = acc + __ldg(bb);
}

// ---------------------------------------------------------------------------
extern "C" void kernel_launch(void* const* d_in, const int* in_sizes, int n_in,
                              void* d_out, int out_size) {
    const float* x      = (const float*)d_in[0];  // specific_user [B,H]
    const float* shr    = (const float*)d_in[1];  // shared_user   [B,H]
    const float* protos = (const float*)d_in[2];  // [P,H]
    const float* llw    = (const float*)d_in[3];  // [C,P]
    const float* W      = (const float*)d_in[4];  // [1,H,H]
    const float* bb     = (const float*)d_in[5];  // [1]
    const int*   flag   = (const int*)d_in[6];    // scalar
    float* out = (float*)d_out;

    k_init  <<<Pp + 1, 256>>>(protos);
    k_dist  <<<Bsz / 64, 256>>>(x, protos, llw, out);
    k_argmax<<<1, 32>>>(flag);
    k_u     <<<32, 256>>>(protos, W);
    k_pos   <<<Bsz / 8, 256>>>(shr, bb, out);
}

// round 2
// speedup vs baseline: 1.0406x; 1.0406x over previous
#include <cuda_runtime.h>
#include <math.h>
#include <stdint.h>

#define Bsz 16384
#define Hd  1024
#define Cc  2
#define PPCc 24
#define Pp  48
#define EPSf 1e-4f

// Output layout (concatenated reference tuple, all fp32):
//   pos      [B,1]   at 0
//   shared   [B,H]   at B
//   logits   [B,C]   at B + B*H
//   distance [B,P]   at B + B*H + B*C
#define POS_OFF    ((size_t)0)
#define SHARED_OFF ((size_t)Bsz)
#define LOGITS_OFF (SHARED_OFF + (size_t)Bsz * Hd)
#define DIST_OFF   (LOGITS_OFF + (size_t)Bsz * Cc)

// Scratch (no device allocs allowed)
__device__ float g_p2[Pp];
__device__ float g_simSum[Pp];
__device__ int   g_jstar;
__device__ float g_u[Hd];

__device__ __forceinline__ uint32_t f2tf(float f) {
    uint32_t r;
    asm("cvt.rna.tf32.f32 %0, %1;" : "=r"(r) : "f"(f));
    return r;
}

// ---------------------------------------------------------------------------
// Kernel 1: block 0 zeroes accumulators; blocks 1..48 compute ||proto_p||^2
// ---------------------------------------------------------------------------
__global__ void k_init(const float* __restrict__ protos) {
    const int b   = blockIdx.x;
    const int tid = threadIdx.x;
    if (b == 0) {
        if (tid < Pp) g_simSum[tid] = 0.f;
        for (int i = tid; i < Hd; i += blockDim.x) g_u[i] = 0.f;
        return;
    }
    const int p = b - 1;
    const float* pr = protos + (size_t)p * Hd;
    float s = 0.f;
    for (int t = tid; t < Hd; t += 256) { float v = pr[t]; s = fmaf(v, v, s); }
    __shared__ float red[8];
    for (int o = 16; o; o >>= 1) s += __shfl_xor_sync(0xffffffffu, s, o);
    const int lane = tid & 31, w = tid >> 5;
    if (lane == 0) red[w] = s;
    __syncthreads();
    if (w == 0) {
        s = (lane < 8) ? red[lane] : 0.f;
        for (int o = 4; o; o >>= 1) s += __shfl_xor_sync(0xffffffffu, s, o);
        if (lane == 0) g_p2[p] = s;
    }
}

// ---------------------------------------------------------------------------
// Kernel 2: distance GEMM via tf32 mma.sync (m16n8k8).
// Block tile 128 rows x 48 protos; 8 warps, warp w owns rows [16w,16w+16).
// K staged through smem in 32-wide tiles with register double-buffering.
// x^2 accumulated from the loaded tiles (no extra gmem pass).
// Epilogue: distance write, log-similarity, logits, per-proto sim sums.
// ---------------------------------------------------------------------------
__global__ __launch_bounds__(256, 1) void k_dist(
    const float* __restrict__ x, const float* __restrict__ protos,
    const float* __restrict__ llw, float* __restrict__ out) {
    __shared__ uint32_t xs[128 * 36];
    __shared__ uint32_t ps[48 * 36];
    __shared__ float x2s[128];
    __shared__ float p2s[48];
    __shared__ float wks[96];
    __shared__ float logit_s[256];
    __shared__ float simPart[48];

    const int tid  = threadIdx.x;
    const int lane = tid & 31, warp = tid >> 5;
    const int row0 = blockIdx.x * 128;
    const int g  = lane >> 2;     // group id 0..7
    const int t4 = lane & 3;      // thread-in-group 0..3

    if (tid < 128) x2s[tid] = 0.f;
    if (tid < 48)  { p2s[tid] = g_p2[tid]; simPart[tid] = 0.f; }
    if (tid < 96)  wks[tid] = llw[tid];
    logit_s[tid] = 0.f;

    // load geometry: each thread owns fixed rows / k-quarter across all stages
    const int xrow = tid >> 3;                 // 0..31 (+32*i)
    const int xk4  = (tid & 7) << 2;           // k offset (floats) in 32-tile
    const float* xbase = x + (size_t)(row0 + xrow) * Hd + xk4;
    const int prow0 = tid >> 3;                // 0..31
    const int prow1 = 32 + (tid >> 3);         // valid for tid < 128
    const float* pbase0 = protos + (size_t)prow0 * Hd + xk4;
    const float* pbase1 = protos + (size_t)prow1 * Hd + xk4;
    const bool   phas1  = (tid < 128);

    float4 xc0 = *(const float4*)(xbase + (size_t)0  * Hd);
    float4 xc1 = *(const float4*)(xbase + (size_t)32 * Hd);
    float4 xc2 = *(const float4*)(xbase + (size_t)64 * Hd);
    float4 xc3 = *(const float4*)(xbase + (size_t)96 * Hd);
    float4 pc0 = *(const float4*)pbase0;
    float4 pc1 = phas1 ? *(const float4*)pbase1 : make_float4(0.f, 0.f, 0.f, 0.f);

    float acc[6][4];
#pragma unroll
    for (int n = 0; n < 6; n++)
#pragma unroll
        for (int q = 0; q < 4; q++) acc[n][q] = 0.f;
    float sq0 = 0.f, sq1 = 0.f, sq2 = 0.f, sq3 = 0.f;

    const int Rg  = warp * 16 + g;             // A-frag rows Rg and Rg+8

    for (int s = 0; s < 32; s++) {
        if (s) __syncthreads();                // previous mma done with smem

        // prefetch next stage into regs (LDG latency hidden by store+mma)
        float4 xn0, xn1, xn2, xn3, pn0, pn1;
        if (s < 31) {
            const int ko = (s + 1) * 32;
            xn0 = *(const float4*)(xbase + (size_t)0  * Hd + ko);
            xn1 = *(const float4*)(xbase + (size_t)32 * Hd + ko);
            xn2 = *(const float4*)(xbase + (size_t)64 * Hd + ko);
            xn3 = *(const float4*)(xbase + (size_t)96 * Hd + ko);
            pn0 = *(const float4*)(pbase0 + ko);
            if (phas1) pn1 = *(const float4*)(pbase1 + ko);
        }

        // store current tiles (tf32-converted) + accumulate x^2 from raw fp32
        {
            uint32_t* d;
            d = &xs[(xrow +  0) * 36 + xk4];
            sq0 = fmaf(xc0.x, xc0.x, sq0); sq0 = fmaf(xc0.y, xc0.y, sq0);
            sq0 = fmaf(xc0.z, xc0.z, sq0); sq0 = fmaf(xc0.w, xc0.w, sq0);
            d[0] = f2tf(xc0.x); d[1] = f2tf(xc0.y); d[2] = f2tf(xc0.z); d[3] = f2tf(xc0.w);
            d = &xs[(xrow + 32) * 36 + xk4];
            sq1 = fmaf(xc1.x, xc1.x, sq1); sq1 = fmaf(xc1.y, xc1.y, sq1);
            sq1 = fmaf(xc1.z, xc1.z, sq1); sq1 = fmaf(xc1.w, xc1.w, sq1);
            d[0] = f2tf(xc1.x); d[1] = f2tf(xc1.y); d[2] = f2tf(xc1.z); d[3] = f2tf(xc1.w);
            d = &xs[(xrow + 64) * 36 + xk4];
            sq2 = fmaf(xc2.x, xc2.x, sq2); sq2 = fmaf(xc2.y, xc2.y, sq2);
            sq2 = fmaf(xc2.z, xc2.z, sq2); sq2 = fmaf(xc2.w, xc2.w, sq2);
            d[0] = f2tf(xc2.x); d[1] = f2tf(xc2.y); d[2] = f2tf(xc2.z); d[3] = f2tf(xc2.w);
            d = &xs[(xrow + 96) * 36 + xk4];
            sq3 = fmaf(xc3.x, xc3.x, sq3); sq3 = fmaf(xc3.y, xc3.y, sq3);
            sq3 = fmaf(xc3.z, xc3.z, sq3); sq3 = fmaf(xc3.w, xc3.w, sq3);
            d[0] = f2tf(xc3.x); d[1] = f2tf(xc3.y); d[2] = f2tf(xc3.z); d[3] = f2tf(xc3.w);
            d = &ps[prow0 * 36 + xk4];
            d[0] = f2tf(pc0.x); d[1] = f2tf(pc0.y); d[2] = f2tf(pc0.z); d[3] = f2tf(pc0.w);
            if (phas1) {
                d = &ps[prow1 * 36 + xk4];
                d[0] = f2tf(pc1.x); d[1] = f2tf(pc1.y); d[2] = f2tf(pc1.z); d[3] = f2tf(pc1.w);
            }
        }
        __syncthreads();

        // mma phase: 4 k-chunks x 6 n-tiles
#pragma unroll
        for (int kc = 0; kc < 32; kc += 8) {
            const uint32_t a0 = xs[(Rg    ) * 36 + kc + t4];
            const uint32_t a1 = xs[(Rg + 8) * 36 + kc + t4];
            const uint32_t a2 = xs[(Rg    ) * 36 + kc + t4 + 4];
            const uint32_t a3 = xs[(Rg + 8) * 36 + kc + t4 + 4];
#pragma unroll
            for (int nt = 0; nt < 6; nt++) {
                const uint32_t b0 = ps[(nt * 8 + g) * 36 + kc + t4];
                const uint32_t b1 = ps[(nt * 8 + g) * 36 + kc + t4 + 4];
                asm volatile(
                    "mma.sync.aligned.m16n8k8.row.col.f32.tf32.tf32.f32 "
                    "{%0,%1,%2,%3}, {%4,%5,%6,%7}, {%8,%9}, {%0,%1,%2,%3};"
                    : "+f"(acc[nt][0]), "+f"(acc[nt][1]),
                      "+f"(acc[nt][2]), "+f"(acc[nt][3])
                    : "r"(a0), "r"(a1), "r"(a2), "r"(a3), "r"(b0), "r"(b1));
            }
        }

        if (s < 31) {
            xc0 = xn0; xc1 = xn1; xc2 = xn2; xc3 = xn3;
            pc0 = pn0; if (phas1) pc1 = pn1;
        }
    }
    __syncthreads();

    // x^2 reduction (8 partials per row)
    atomicAdd(&x2s[xrow +  0], sq0);
    atomicAdd(&x2s[xrow + 32], sq1);
    atomicAdd(&x2s[xrow + 64], sq2);
    atomicAdd(&x2s[xrow + 96], sq3);
    __syncthreads();

    // epilogue
    const int ra = Rg, rb = Rg + 8;
    const float x2a = x2s[ra], x2b = x2s[rb];
    float lgA0 = 0.f, lgA1 = 0.f, lgB0 = 0.f, lgB1 = 0.f;
    float* dd = out + DIST_OFF + (size_t)row0 * 48;
#pragma unroll
    for (int nt = 0; nt < 6; nt++) {
        const int c0 = nt * 8 + t4 * 2, c1 = c0 + 1;
        const float dA0 = fmaf(-2.f, acc[nt][0], x2a + p2s[c0]);
        const float dA1 = fmaf(-2.f, acc[nt][1], x2a + p2s[c1]);
        const float dB0 = fmaf(-2.f, acc[nt][2], x2b + p2s[c0]);
        const float dB1 = fmaf(-2.f, acc[nt][3], x2b + p2s[c1]);
        *(float2*)(dd + (size_t)ra * 48 + c0) = make_float2(dA0, dA1);
        *(float2*)(dd + (size_t)rb * 48 + c0) = make_float2(dB0, dB1);
        const float sA0 = logf((dA0 + 1.f) / (dA0 + EPSf));
        const float sA1 = logf((dA1 + 1.f) / (dA1 + EPSf));
        const float sB0 = logf((dB0 + 1.f) / (dB0 + EPSf));
        const float sB1 = logf((dB1 + 1.f) / (dB1 + EPSf));
        lgA0 = fmaf(sA0, wks[c0], lgA0); lgA0 = fmaf(sA1, wks[c1], lgA0);
        lgA1 = fmaf(sA0, wks[48 + c0], lgA1); lgA1 = fmaf(sA1, wks[48 + c1], lgA1);
        lgB0 = fmaf(sB0, wks[c0], lgB0); lgB0 = fmaf(sB1, wks[c1], lgB0);
        lgB1 = fmaf(sB0, wks[48 + c0], lgB1); lgB1 = fmaf(sB1, wks[48 + c1], lgB1);
        atomicAdd(&simPart[c0], sA0 + sB0);
        atomicAdd(&simPart[c1], sA1 + sB1);
    }
    atomicAdd(&logit_s[ra * 2 + 0], lgA0);
    atomicAdd(&logit_s[ra * 2 + 1], lgA1);
    atomicAdd(&logit_s[rb * 2 + 0], lgB0);
    atomicAdd(&logit_s[rb * 2 + 1], lgB1);
    __syncthreads();

    out[LOGITS_OFF + (size_t)row0 * 2 + tid] = logit_s[tid];
    if (tid < 48) atomicAdd(&g_simSum[tid], simPart[tid]);
}

// ---------------------------------------------------------------------------
// Kernel 3: argmax over the class's 24 prototype column sums (first-max ties)
// ---------------------------------------------------------------------------
__global__ void k_argmax(const int* __restrict__ flag) {
    const int idx  = (flag[0] != 0) ? 1 : 0;
    const int lane = threadIdx.x;
    float v = (lane < PPCc) ? g_simSum[idx * PPCc + lane] : -INFINITY;
    int bj = lane;
    for (int o = 16; o; o >>= 1) {
        const float ov = __shfl_xor_sync(0xffffffffu, v, o);
        const int   oj = __shfl_xor_sync(0xffffffffu, bj, o);
        if (ov > v || (ov == v && oj < bj)) { v = ov; bj = oj; }
    }
    if (lane == 0) g_jstar = idx * PPCc + bj;
}

// ---------------------------------------------------------------------------
// Kernel 4: u[j] = sum_i v_i * W[i][j], v = protos[g_jstar]
// 128 blocks x 8 rows each; float atomics into g_u
// ---------------------------------------------------------------------------
__global__ __launch_bounds__(256) void k_u(
    const float* __restrict__ protos, const float* __restrict__ W) {
    __shared__ float vsh[8];
    const int b = blockIdx.x, t = threadIdx.x;
    if (t < 8) vsh[t] = protos[(size_t)g_jstar * Hd + b * 8 + t];
    __syncthreads();
    float a0 = 0.f, a1 = 0.f, a2 = 0.f, a3 = 0.f;
    const float* Wp = W + (size_t)b * 8 * Hd + (size_t)t * 4;
#pragma unroll
    for (int i = 0; i < 8; i++) {
        const float4 w = *(const float4*)(Wp + (size_t)i * Hd);
        const float vi = vsh[i];
        a0 = fmaf(vi, w.x, a0);
        a1 = fmaf(vi, w.y, a1);
        a2 = fmaf(vi, w.z, a2);
        a3 = fmaf(vi, w.w, a3);
    }
    atomicAdd(&g_u[t * 4 + 0], a0);
    atomicAdd(&g_u[t * 4 + 1], a1);
    atomicAdd(&g_u[t * 4 + 2], a2);
    atomicAdd(&g_u[t * 4 + 3], a3);
}

// ---------------------------------------------------------------------------
// Kernel 5: fused shared_user copy-out + pos[b] = dot(u, shared[b]) + bias
// 1 warp per row, 8 rows per block
// ---------------------------------------------------------------------------
__global__ __launch_bounds__(256) void k_pos(
    const float* __restrict__ shr, const float* __restrict__ bb,
    float* __restrict__ out) {
    __shared__ float us[Hd];
    for (int i = threadIdx.x; i < Hd; i += 256) us[i] = g_u[i];
    __syncthreads();
    const int warp = threadIdx.x >> 5, lane = threadIdx.x & 31;
    const int r = blockIdx.x * 8 + warp;
    const float4* src = (const float4*)(shr + (size_t)r * Hd);
    float4*       dst = (float4*)(out + SHARED_OFF + (size_t)r * Hd);
    const float4* uf  = (const float4*)us;
    float acc = 0.f;
#pragma unroll
    for (int t = lane; t < Hd / 4; t += 32) {
        const float4 v  = src[t];
        dst[t] = v;
        const float4 u4 = uf[t];
        acc = fmaf(v.x, u4.x, acc);
        acc = fmaf(v.y, u4.y, acc);
        acc = fmaf(v.z, u4.z, acc);
        acc = fmaf(v.w, u4.w, acc);
    }
    for (int o = 16; o; o >>= 1) acc += __shfl_xor_sync(0xffffffffu, acc, o);
    if (lane == 0) out[POS_OFF + r] = acc + __ldg(bb);
}

// ---------------------------------------------------------------------------
extern "C" void kernel_launch(void* const* d_in, const int* in_sizes, int n_in,
                              void* d_out, int out_size) {
    const float* x      = (const float*)d_in[0];  // specific_user [B,H]
    const float* shr    = (const float*)d_in[1];  // shared_user   [B,H]
    const float* protos = (const float*)d_in[2];  // [P,H]
    const float* llw    = (const float*)d_in[3];  // [C,P]
    const float* W      = (const float*)d_in[4];  // [1,H,H]
    const float* bb     = (const float*)d_in[5];  // [1]
    const int*   flag   = (const int*)d_in[6];    // scalar
    float* out = (float*)d_out;

    k_init  <<<Pp + 1, 256>>>(protos);
    k_dist  <<<Bsz / 128, 256>>>(x, protos, llw, out);
    k_argmax<<<1, 32>>>(flag);
    k_u     <<<128, 256>>>(protos, W);
    k_pos   <<<Bsz / 8, 256>>>(shr, bb, out);
}